// round 4
// baseline (speedup 1.0000x reference)
#include <cuda_runtime.h>

typedef unsigned long long ull;

// ---- f32x2 packed helpers (Blackwell) ----
__device__ __forceinline__ ull ffma2(ull a, ull b, ull c) {
    ull d;
    asm("fma.rn.f32x2 %0, %1, %2, %3;" : "=l"(d) : "l"(a), "l"(b), "l"(c));
    return d;
}
__device__ __forceinline__ ull pack2(float lo, float hi) {
    ull r;
    asm("mov.b64 %0, {%1, %2};" : "=l"(r) : "f"(lo), "f"(hi));
    return r;
}
__device__ __forceinline__ void unpack2(ull v, float& lo, float& hi) {
    asm("mov.b64 {%0, %1}, %2;" : "=f"(lo), "=f"(hi) : "l"(v));
}

static constexpr int THREADS = 256;
static constexpr int R = 2;                 // rows per thread
static constexpr int TILE = THREADS * R;    // 512 rows per CTA

// SMEM layout (float offsets). XS holds HALF the features at a time (2-phase k-staging).
static constexpr int XS_STRIDE = 33;        // 33 mod 32 == 1 -> conflict-free reads
static constexpr int W1_STRIDE = 34;
static constexpr int W2_STRIDE = 18;
static constexpr int OFF_XS  = 0;                         // 512*33 = 16896
static constexpr int OFF_WT1 = OFF_XS + TILE * XS_STRIDE; // 16896 : 64*34 = 2176
static constexpr int OFF_WT2 = OFF_WT1 + 64 * W1_STRIDE;  // 19072 : 32*18 = 576
static constexpr int OFF_W3  = OFF_WT2 + 32 * W2_STRIDE;  // 19648 : 16
static constexpr int OFF_B1  = OFF_W3 + 16;               // 19664 : 32
static constexpr int OFF_B2  = OFF_B1 + 32;               // 19696 : 16
static constexpr int SMEM_FLOATS = OFF_B2 + 16;           // 19712
static constexpr int SMEM_BYTES  = SMEM_FLOATS * 4;       // 78848 -> 2 CTAs/SM

__global__ void __launch_bounds__(THREADS, 2)
hybridq_kernel(const float* __restrict__ x_q,
               const float* __restrict__ x_c,
               const float* __restrict__ q_params,
               const float* __restrict__ w1,
               const float* __restrict__ b1,
               const float* __restrict__ w2,
               const float* __restrict__ b2,
               const float* __restrict__ w3,
               const float* __restrict__ b3,
               float* __restrict__ out,
               int B)
{
    extern __shared__ float sm[];
    float* XS  = sm + OFF_XS;
    float* WT1 = sm + OFF_WT1;
    float* WT2 = sm + OFF_WT2;
    float* W3S = sm + OFF_W3;
    float* B1S = sm + OFF_B1;
    float* B2S = sm + OFF_B2;

    const int tid = threadIdx.x;
    const int r0  = blockIdx.x * TILE;
    const int rows = min(TILE, B - r0);

    // ---- stage weights transposed (output-pairs contiguous) ----
    #pragma unroll
    for (int i = 0; i < 8; ++i) {
        int idx = tid + 256 * i;                // w1 is [32][64]
        int t = idx >> 6, k = idx & 63;
        WT1[k * W1_STRIDE + t] = w1[idx];
    }
    #pragma unroll
    for (int i = 0; i < 2; ++i) {
        int idx = tid + 256 * i;                // w2 is [16][32]
        int m = idx >> 5, j = idx & 31;
        WT2[j * W2_STRIDE + m] = w2[idx];
    }
    if (tid < 16) W3S[tid] = w3[tid];
    if (tid < 32) B1S[tid] = b1[tid];
    if (tid < 16) B2S[tid] = b2[tid];

    // ---- q_out in registers (closed-form circuit: cos(x1+w1)*cos(x2+w2)) ----
    const float qp1 = __ldg(q_params + 1);
    const float qp2 = __ldg(q_params + 2);
    ull qq[R];
    #pragma unroll
    for (int r = 0; r < R; ++r) {
        int row = tid + 256 * r;
        float q = 0.0f;
        if (row < rows) {
            long long g = (long long)(r0 + row) * 3;
            q = __cosf(x_q[g + 1] + qp1) * __cosf(x_q[g + 2] + qp2);
        }
        qq[r] = pack2(q, q);
    }

    // ---- phase 0 staging: x_c cols 0..31 (each warp copies one 128B row-chunk) ----
    {
        const int n = rows * 32;
        for (int i = tid; i < n; i += THREADS) {
            int row = i >> 5, c = i & 31;
            XS[row * XS_STRIDE + c] = x_c[((long long)(r0 + row)) * 63 + c];
        }
    }
    __syncthreads();

    int xb[R];
    #pragma unroll
    for (int r = 0; r < R; ++r) xb[r] = (tid + 256 * r) * XS_STRIDE;

    // ================= layer 1: h1[32] = relu(W1 @ x + b1) =================
    // acc[r][p] holds outputs (2p, 2p+1) in the two f32 lanes.
    ull acc[R][16];
    #pragma unroll
    for (int p = 0; p < 16; ++p) {
        const ull bp = *reinterpret_cast<const ull*>(B1S + 2 * p);
        #pragma unroll
        for (int r = 0; r < R; ++r) acc[r][p] = bp;
    }

    // k = 0 : q_out feature
    #pragma unroll
    for (int p = 0; p < 16; ++p) {
        const ull wv = *reinterpret_cast<const ull*>(WT1 + 2 * p);
        #pragma unroll
        for (int r = 0; r < R; ++r) acc[r][p] = ffma2(wv, qq[r], acc[r][p]);
    }

    // k = 1..32 : x_c cols 0..31 (phase-0 buffer)
    #pragma unroll 8
    for (int k = 1; k <= 32; ++k) {
        ull xx[R];
        #pragma unroll
        for (int r = 0; r < R; ++r) {
            float x = XS[xb[r] + (k - 1)];
            xx[r] = pack2(x, x);
        }
        const float* wrow = WT1 + k * W1_STRIDE;
        #pragma unroll
        for (int p = 0; p < 16; ++p) {
            const ull wv = *reinterpret_cast<const ull*>(wrow + 2 * p);
            #pragma unroll
            for (int r = 0; r < R; ++r) acc[r][p] = ffma2(wv, xx[r], acc[r][p]);
        }
    }

    // ---- phase 1 staging: x_c cols 32..62 overwrite the same buffer ----
    __syncthreads();
    {
        const int n = rows * 31;
        for (int i = tid; i < n; i += THREADS) {
            int row = i / 31, c = i - row * 31;
            XS[row * XS_STRIDE + c] = x_c[((long long)(r0 + row)) * 63 + 32 + c];
        }
    }
    __syncthreads();

    // k = 33..63 : x_c cols 32..62 (phase-1 buffer)
    #pragma unroll 8
    for (int k = 33; k < 64; ++k) {
        ull xx[R];
        #pragma unroll
        for (int r = 0; r < R; ++r) {
            float x = XS[xb[r] + (k - 33)];
            xx[r] = pack2(x, x);
        }
        const float* wrow = WT1 + k * W1_STRIDE;
        #pragma unroll
        for (int p = 0; p < 16; ++p) {
            const ull wv = *reinterpret_cast<const ull*>(wrow + 2 * p);
            #pragma unroll
            for (int r = 0; r < R; ++r) acc[r][p] = ffma2(wv, xx[r], acc[r][p]);
        }
    }

    float h1[R][32];
    #pragma unroll
    for (int r = 0; r < R; ++r)
        #pragma unroll
        for (int p = 0; p < 16; ++p) {
            float lo, hi;
            unpack2(acc[r][p], lo, hi);
            h1[r][2 * p]     = fmaxf(lo, 0.0f);
            h1[r][2 * p + 1] = fmaxf(hi, 0.0f);
        }

    // ================= layer 2: h2[16] = relu(W2 @ h1 + b2) =================
    ull a2[R][8];
    #pragma unroll
    for (int p = 0; p < 8; ++p) {
        const ull bp = *reinterpret_cast<const ull*>(B2S + 2 * p);
        #pragma unroll
        for (int r = 0; r < R; ++r) a2[r][p] = bp;
    }
    #pragma unroll
    for (int j = 0; j < 32; ++j) {
        const float* w2r = WT2 + j * W2_STRIDE;
        ull xx[R];
        #pragma unroll
        for (int r = 0; r < R; ++r) xx[r] = pack2(h1[r][j], h1[r][j]);
        #pragma unroll
        for (int p = 0; p < 8; ++p) {
            const ull wv = *reinterpret_cast<const ull*>(w2r + 2 * p);
            #pragma unroll
            for (int r = 0; r < R; ++r) a2[r][p] = ffma2(wv, xx[r], a2[r][p]);
        }
    }

    float h2[R][16];
    #pragma unroll
    for (int r = 0; r < R; ++r)
        #pragma unroll
        for (int p = 0; p < 8; ++p) {
            float lo, hi;
            unpack2(a2[r][p], lo, hi);
            h2[r][2 * p]     = fmaxf(lo, 0.0f);
            h2[r][2 * p + 1] = fmaxf(hi, 0.0f);
        }

    // ================= layer 3: out = w3 . h2 + b3 =================
    const float b3v = __ldg(b3);
    #pragma unroll
    for (int r = 0; r < R; ++r) {
        ull a3 = pack2(b3v, 0.0f);
        #pragma unroll
        for (int v = 0; v < 8; ++v) {
            const ull wv = *reinterpret_cast<const ull*>(W3S + 2 * v);
            a3 = ffma2(wv, pack2(h2[r][2 * v], h2[r][2 * v + 1]), a3);
        }
        float lo, hi;
        unpack2(a3, lo, hi);
        int row = tid + 256 * r;
        if (row < rows) out[r0 + row] = lo + hi;
    }
}

extern "C" void kernel_launch(void* const* d_in, const int* in_sizes, int n_in,
                              void* d_out, int out_size)
{
    const float* x_q      = (const float*)d_in[0];
    const float* x_c      = (const float*)d_in[1];
    const float* q_params = (const float*)d_in[2];
    const float* w1       = (const float*)d_in[3];
    const float* b1       = (const float*)d_in[4];
    const float* w2       = (const float*)d_in[5];
    const float* b2       = (const float*)d_in[6];
    const float* w3       = (const float*)d_in[7];
    const float* b3       = (const float*)d_in[8];
    float* out            = (float*)d_out;

    const int B = in_sizes[0] / 3;
    const int blocks = (B + TILE - 1) / TILE;

    cudaFuncSetAttribute(hybridq_kernel,
                         cudaFuncAttributeMaxDynamicSharedMemorySize, SMEM_BYTES);

    hybridq_kernel<<<blocks, THREADS, SMEM_BYTES>>>(
        x_q, x_c, q_params, w1, b1, w2, b2, w3, b3, out, B);
}